// round 7
// baseline (speedup 1.0000x reference)
#include <cuda_runtime.h>
#include <math.h>

#define LVL 3
#define HH 180
#define WIW 180
#define HW 32400
#define CC 128
#define HEADS 8
#define PP 4
#define DFF 1024
#define MQ (LVL*HW)           // 97200

// ---------------- scratch (device globals; no allocation allowed) ----------------
__device__ float g_wT[9*256*128];                 // conv weights [tap][ci][co]
__device__ float g_queries[(size_t)LVL*HW*CC];    // [l][p][c]
__device__ float g_value[(size_t)LVL*HW*CC];      // [l][h][p][dh]
__device__ float g_offattn[(size_t)LVL*HW*96];    // [l][p][64 off | 32 logits]
__device__ float g_attnout[(size_t)HW*CC];        // [p][c]
__device__ float g_src[(size_t)HW*CC];            // after LN1
__device__ float g_hidden[(size_t)HW*DFF];        // FFN hidden

// ---------------- weight transpose: conv_w [o][i][ky][kx] -> wT [t][i][o] ----------------
__global__ void wtrans_kernel(const float* __restrict__ conv_w) {
    int idx = blockIdx.x * 256 + threadIdx.x;
    if (idx >= 9*256*128) return;
    int o = idx & 127;
    int i = (idx >> 7) & 255;
    int t = idx >> 15;
    g_wT[idx] = conv_w[(o*256 + i)*9 + t];
}

// ---------------- conv as implicit GEMM: M=HW (per level), N=128, K=9*256 ----------------
// Flattened 72-chunk loop (9 taps x 8 k-subchunks) with register prefetch of the
// next chunk's A tile (predicated shifted gather) to hide L2 latency under FMAs.
__global__ __launch_bounds__(256) void conv_kernel(const float* __restrict__ src,
                                                   const float* __restrict__ conv_b) {
    __shared__ __align__(16) float As[32][132];
    __shared__ __align__(16) float Bs[32][132];
    const int l  = blockIdx.y;
    const int m0 = blockIdx.x * 128;
    const int tid = threadIdx.x;
    const int tx = tid & 15, ty = tid >> 4;

    float acc[8][8];
#pragma unroll
    for (int i = 0; i < 8; ++i)
#pragma unroll
        for (int j = 0; j < 8; ++j) acc[i][j] = 0.f;

    const float* src0 = src;                         // frame 0 (target)
    const float* srcl = src + (size_t)l * HW * CC;   // frame l

    // Hoist per-load-slot row coordinates (invariant across chunks)
    int ry_[4], rx_[4];
    bool rv_[4];
#pragma unroll
    for (int it = 0; it < 4; ++it) {
        int li = tid + it * 256;
        int r  = li >> 3;
        int gm = m0 + r;
        rv_[it] = (gm < HW);
        int gmc = rv_[it] ? gm : 0;
        ry_[it] = gmc / WIW;
        rx_[it] = gmc % WIW;
    }

    float4 pa[4];
    // prefetch chunk u=0: t=0 (dy=-1,dx=-1), c0=0 -> src0, cb=0
#pragma unroll
    for (int it = 0; it < 4; ++it) {
        int li = tid + it * 256;
        int kv = (li & 7) << 2;
        pa[it] = make_float4(0.f, 0.f, 0.f, 0.f);
        int y = ry_[it] - 1;
        int x = rx_[it] - 1;
        if (rv_[it] && y >= 0 && x >= 0)
            pa[it] = *(const float4*)(src0 + (size_t)(y * WIW + x) * CC + kv);
    }

    for (int u = 0; u < 72; ++u) {
        const int t  = u >> 3;
        const int c0 = (u & 7) * 32;
        __syncthreads();
        // A tile from prefetch registers
#pragma unroll
        for (int it = 0; it < 4; ++it) {
            int li = tid + it * 256;
            int r  = li >> 3;
            int kv = (li & 7) << 2;
            As[kv+0][r] = pa[it].x; As[kv+1][r] = pa[it].y;
            As[kv+2][r] = pa[it].z; As[kv+3][r] = pa[it].w;
        }
        // B tile: 32 x 128 from transposed weights
        const float* wb = g_wT + (size_t)(t * 256 + c0) * 128;
#pragma unroll
        for (int it = 0; it < 4; ++it) {
            int li = tid + it * 256;
            int kk = li >> 5;
            int nv = (li & 31) << 2;
            *(float4*)&Bs[kk][nv] = *(const float4*)(wb + kk * 128 + nv);
        }
        __syncthreads();
        // prefetch next chunk's A tile
        if (u + 1 < 72) {
            const int t2  = (u + 1) >> 3;
            const int c02 = ((u + 1) & 7) * 32;
            const int dy2 = t2 / 3 - 1, dx2 = t2 % 3 - 1;
            const float* sb2 = (c02 < 128) ? src0 : srcl;
            const int cb2 = (c02 < 128) ? c02 : (c02 - 128);
#pragma unroll
            for (int it = 0; it < 4; ++it) {
                int li = tid + it * 256;
                int kv = (li & 7) << 2;
                pa[it] = make_float4(0.f, 0.f, 0.f, 0.f);
                int y = ry_[it] + dy2;
                int x = rx_[it] + dx2;
                if (rv_[it] && y >= 0 && y < HH && x >= 0 && x < WIW)
                    pa[it] = *(const float4*)(sb2 + (size_t)(y * WIW + x) * CC + cb2 + kv);
            }
        }
#pragma unroll
        for (int k = 0; k < 32; ++k) {
            float a[8], b[8];
            *(float4*)&a[0] = *(const float4*)&As[k][ty*8];
            *(float4*)&a[4] = *(const float4*)&As[k][ty*8+4];
            *(float4*)&b[0] = *(const float4*)&Bs[k][tx*8];
            *(float4*)&b[4] = *(const float4*)&Bs[k][tx*8+4];
#pragma unroll
            for (int i = 0; i < 8; ++i)
#pragma unroll
                for (int j = 0; j < 8; ++j)
                    acc[i][j] = fmaf(a[i], b[j], acc[i][j]);
        }
    }
    float* outp = g_queries + (size_t)l * HW * CC;
#pragma unroll
    for (int i = 0; i < 8; ++i) {
        int row = m0 + ty*8 + i;
        if (row < HW) {
#pragma unroll
            for (int j = 0; j < 8; ++j) {
                int col = tx*8 + j;
                outp[(size_t)row*CC + col] = acc[i][j] + conv_b[col];
            }
        }
    }
}

// ---------------- value projection: [MQ x 128] @ [128 x 128], store [l][h][p][dh] ----------------
__global__ __launch_bounds__(256) void value_kernel(const float* __restrict__ src,
                                                    const float* __restrict__ Wv,
                                                    const float* __restrict__ bv) {
    __shared__ __align__(16) float As[32][132];
    __shared__ __align__(16) float Bs[32][132];
    const int m0 = blockIdx.x * 128;
    const int tid = threadIdx.x;
    const int tx = tid & 15, ty = tid >> 4;
    float acc[8][8];
#pragma unroll
    for (int i = 0; i < 8; ++i)
#pragma unroll
        for (int j = 0; j < 8; ++j) acc[i][j] = 0.f;

    // A prefetch registers (next k-chunk)
    float4 pa[4];
#pragma unroll
    for (int it = 0; it < 4; ++it) {
        int li = tid + it * 256;
        int gm = m0 + (li >> 3);
        pa[it] = make_float4(0.f,0.f,0.f,0.f);
        if (gm < MQ) pa[it] = *(const float4*)(src + (size_t)gm * CC + ((li & 7) << 2));
    }

    for (int cc = 0; cc < 4; ++cc) {
        const int k0 = cc * 32;
        __syncthreads();
#pragma unroll
        for (int it = 0; it < 4; ++it) {
            int li = tid + it * 256;
            int r  = li >> 3;
            int kv = (li & 7) << 2;
            As[kv+0][r] = pa[it].x; As[kv+1][r] = pa[it].y;
            As[kv+2][r] = pa[it].z; As[kv+3][r] = pa[it].w;
        }
#pragma unroll
        for (int it = 0; it < 4; ++it) {
            int li = tid + it * 256;
            int kk = li >> 5;
            int nv = (li & 31) << 2;
            *(float4*)&Bs[kk][nv] = *(const float4*)(Wv + (size_t)(k0 + kk) * CC + nv);
        }
        __syncthreads();
        if (cc < 3) {
            const int kn = k0 + 32;
#pragma unroll
            for (int it = 0; it < 4; ++it) {
                int li = tid + it * 256;
                int gm = m0 + (li >> 3);
                pa[it] = make_float4(0.f,0.f,0.f,0.f);
                if (gm < MQ) pa[it] = *(const float4*)(src + (size_t)gm * CC + kn + ((li & 7) << 2));
            }
        }
#pragma unroll
        for (int k = 0; k < 32; ++k) {
            float a[8], b[8];
            *(float4*)&a[0] = *(const float4*)&As[k][ty*8];
            *(float4*)&a[4] = *(const float4*)&As[k][ty*8+4];
            *(float4*)&b[0] = *(const float4*)&Bs[k][tx*8];
            *(float4*)&b[4] = *(const float4*)&Bs[k][tx*8+4];
#pragma unroll
            for (int i = 0; i < 8; ++i)
#pragma unroll
                for (int j = 0; j < 8; ++j)
                    acc[i][j] = fmaf(a[i], b[j], acc[i][j]);
        }
    }
#pragma unroll
    for (int i = 0; i < 8; ++i) {
        int row = m0 + ty*8 + i;
        if (row < MQ) {
            int l = row / HW;
            int p = row - l * HW;
#pragma unroll
            for (int j = 0; j < 8; ++j) {
                int col = tx*8 + j;
                int h = col >> 4, dd = col & 15;
                g_value[((size_t)(l*8 + h) * HW + p) * 16 + dd] = acc[i][j] + bv[col];
            }
        }
    }
}

// ---------------- offsets + attn logits: [MQ x 128] @ [128 x 96] ----------------
__global__ __launch_bounds__(256) void offattn_kernel(const float* __restrict__ W_off,
                                                      const float* __restrict__ b_off,
                                                      const float* __restrict__ W_attn,
                                                      const float* __restrict__ b_attn) {
    __shared__ __align__(16) float As[32][132];
    __shared__ __align__(16) float Bs[32][96];
    const int m0 = blockIdx.x * 128;
    const int tid = threadIdx.x;
    const int tx = tid & 15, ty = tid >> 4;
    float acc[8][6];
#pragma unroll
    for (int i = 0; i < 8; ++i)
#pragma unroll
        for (int j = 0; j < 6; ++j) acc[i][j] = 0.f;

    // A prefetch registers
    float4 pa[4];
#pragma unroll
    for (int it = 0; it < 4; ++it) {
        int li = tid + it * 256;
        int gm = m0 + (li >> 3);
        pa[it] = make_float4(0.f,0.f,0.f,0.f);
        if (gm < MQ) pa[it] = *(const float4*)(g_queries + (size_t)gm * CC + ((li & 7) << 2));
    }

    for (int cc = 0; cc < 4; ++cc) {
        const int k0 = cc * 32;
        __syncthreads();
#pragma unroll
        for (int it = 0; it < 4; ++it) {
            int li = tid + it * 256;
            int r  = li >> 3;
            int kv = (li & 7) << 2;
            As[kv+0][r] = pa[it].x; As[kv+1][r] = pa[it].y;
            As[kv+2][r] = pa[it].z; As[kv+3][r] = pa[it].w;
        }
#pragma unroll
        for (int it = 0; it < 3; ++it) {
            int li = tid + it * 256;   // 0..767 = 32*24
            int kk = li / 24;
            int nv = (li % 24) << 2;
            float4 v;
            if (nv < 64) v = *(const float4*)(W_off  + (size_t)(k0 + kk) * 64 + nv);
            else         v = *(const float4*)(W_attn + (size_t)(k0 + kk) * 32 + (nv - 64));
            *(float4*)&Bs[kk][nv] = v;
        }
        __syncthreads();
        if (cc < 3) {
            const int kn = k0 + 32;
#pragma unroll
            for (int it = 0; it < 4; ++it) {
                int li = tid + it * 256;
                int gm = m0 + (li >> 3);
                pa[it] = make_float4(0.f,0.f,0.f,0.f);
                if (gm < MQ) pa[it] = *(const float4*)(g_queries + (size_t)gm * CC + kn + ((li & 7) << 2));
            }
        }
#pragma unroll
        for (int k = 0; k < 32; ++k) {
            float a[8];
            *(float4*)&a[0] = *(const float4*)&As[k][ty*8];
            *(float4*)&a[4] = *(const float4*)&As[k][ty*8+4];
            float b[6];
#pragma unroll
            for (int j = 0; j < 6; ++j) b[j] = Bs[k][tx*6 + j];
#pragma unroll
            for (int i = 0; i < 8; ++i)
#pragma unroll
                for (int j = 0; j < 6; ++j)
                    acc[i][j] = fmaf(a[i], b[j], acc[i][j]);
        }
    }
#pragma unroll
    for (int i = 0; i < 8; ++i) {
        int row = m0 + ty*8 + i;
        if (row < MQ) {
#pragma unroll
            for (int j = 0; j < 6; ++j) {
                int col = tx*6 + j;
                float bias = (col < 64) ? b_off[col] : b_attn[col - 64];
                g_offattn[(size_t)row * 96 + col] = acc[i][j] + bias;
            }
        }
    }
}

// ---------------- deformable sampling + softmax + weighted sum (2 queries/block) ----------------
// Branchless bilinear in 3 waves of 4 points (one wave per level): each wave issues
// its 16 clamped gathers unconditionally (MLP=16) while keeping live registers ~100
// (the fully-unrolled 12-point version needed ~180 regs -> spills).
__global__ __launch_bounds__(256) void sample_kernel(const float* __restrict__ refpts) {
    __shared__ float oa[2][3][96];
    __shared__ float rp[2][6];
    const int q0 = blockIdx.x * 2;
    const int tid = threadIdx.x;
    const int sq = tid >> 7;          // 0 or 1: which query this thread serves
    const int t  = tid & 127;
    const int q  = q0 + sq;

    for (int i = tid; i < 2*288; i += 256) {
        int qq = i / 288;
        int rem = i - qq * 288;
        int l = rem / 96, j = rem - l * 96;
        oa[qq][l][j] = g_offattn[((size_t)l * HW + q0 + qq) * 96 + j];
    }
    if (tid < 12) rp[tid / 6][tid % 6] = refpts[(size_t)q0 * 6 + tid];
    __syncthreads();

    const int h = t >> 4, d = t & 15;
    // softmax over (l, p) = 12 logits for this head
    float mx = -1e30f;
#pragma unroll
    for (int l = 0; l < 3; ++l)
#pragma unroll
        for (int p = 0; p < 4; ++p) mx = fmaxf(mx, oa[sq][l][64 + h*4 + p]);
    float den = 0.f;
#pragma unroll
    for (int l = 0; l < 3; ++l)
#pragma unroll
        for (int p = 0; p < 4; ++p) den += expf(oa[sq][l][64 + h*4 + p] - mx);
    const float inv = 1.0f / den;

    float acc = 0.f;
#pragma unroll
    for (int l = 0; l < 3; ++l) {
        const float rx = rp[sq][l*2 + 0], ry = rp[sq][l*2 + 1];
        const float* vb = g_value + (size_t)(l*8 + h) * HW * 16 + d;

        // Wave: precompute 4 points' masked weights + clamped offsets
        float w00[4], w01[4], w10[4], w11[4], aw[4];
        int o00[4], o01[4], o10[4], o11[4];
#pragma unroll
        for (int p = 0; p < 4; ++p) {
            float ox = oa[sq][l][h*8 + p*2 + 0];
            float oy = oa[sq][l][h*8 + p*2 + 1];
            aw[p] = expf(oa[sq][l][64 + h*4 + p] - mx) * inv;
            float px = (rx + ox * (1.0f/180.0f)) * 180.0f - 0.5f;
            float py = (ry + oy * (1.0f/180.0f)) * 180.0f - 0.5f;
            float xf = floorf(px), yf = floorf(py);
            int x0 = (int)xf, y0 = (int)yf;
            float fx = px - xf, fy = py - yf;
            float vx0 = (x0   >= 0 && x0   < WIW) ? 1.f : 0.f;
            float vx1 = (x0+1 >= 0 && x0+1 < WIW) ? 1.f : 0.f;
            float vy0 = (y0   >= 0 && y0   < HH)  ? 1.f : 0.f;
            float vy1 = (y0+1 >= 0 && y0+1 < HH)  ? 1.f : 0.f;
            int cx0 = min(max(x0,     0), WIW-1);
            int cx1 = min(max(x0 + 1, 0), WIW-1);
            int cy0 = min(max(y0,     0), HH-1);
            int cy1 = min(max(y0 + 1, 0), HH-1);
            w00[p] = (1.f-fx)*(1.f-fy) * vx0 * vy0;
            w01[p] = fx      *(1.f-fy) * vx1 * vy0;
            w10[p] = (1.f-fx)*fy       * vx0 * vy1;
            w11[p] = fx      *fy       * vx1 * vy1;
            o00[p] = (cy0 * WIW + cx0) * 16;
            o01[p] = (cy0 * WIW + cx1) * 16;
            o10[p] = (cy1 * WIW + cx0) * 16;
            o11[p] = (cy1 * WIW + cx1) * 16;
        }

        // Issue the wave's 16 gathers unconditionally (independent -> MLP=16)
        float g00[4], g01[4], g10[4], g11[4];
#pragma unroll
        for (int p = 0; p < 4; ++p) {
            g00[p] = vb[o00[p]];
            g01[p] = vb[o01[p]];
            g10[p] = vb[o10[p]];
            g11[p] = vb[o11[p]];
        }
#pragma unroll
        for (int p = 0; p < 4; ++p) {
            float s = w00[p]*g00[p] + w01[p]*g01[p] + w10[p]*g10[p] + w11[p]*g11[p];
            acc = fmaf(aw[p], s, acc);
        }
    }
    g_attnout[(size_t)q * CC + t] = acc;
}

// ---------------- GEMM (M=HW, N=128, K param) + bias + residual + LayerNorm ----------------
__global__ __launch_bounds__(256) void gemm_ln_kernel(const float* __restrict__ A, int K,
                                                      const float* __restrict__ Bw,
                                                      const float* __restrict__ bias,
                                                      const float* __restrict__ res,
                                                      const float* __restrict__ gamma,
                                                      const float* __restrict__ beta,
                                                      float* __restrict__ out) {
    __shared__ __align__(16) float As[32][132];
    __shared__ __align__(16) float Bs[32][132];
    const int m0 = blockIdx.x * 128;
    const int tid = threadIdx.x;
    const int tx = tid & 15, ty = tid >> 4;
    float acc[8][8];
#pragma unroll
    for (int i = 0; i < 8; ++i)
#pragma unroll
        for (int j = 0; j < 8; ++j) acc[i][j] = 0.f;

    const int chunks = K >> 5;

    // A prefetch registers
    float4 pa[4];
#pragma unroll
    for (int it = 0; it < 4; ++it) {
        int li = tid + it * 256;
        int gm = m0 + (li >> 3);
        pa[it] = make_float4(0.f,0.f,0.f,0.f);
        if (gm < HW) pa[it] = *(const float4*)(A + (size_t)gm * K + ((li & 7) << 2));
    }

    for (int cc = 0; cc < chunks; ++cc) {
        const int k0 = cc * 32;
        __syncthreads();
#pragma unroll
        for (int it = 0; it < 4; ++it) {
            int li = tid + it * 256;
            int r  = li >> 3;
            int kv = (li & 7) << 2;
            As[kv+0][r] = pa[it].x; As[kv+1][r] = pa[it].y;
            As[kv+2][r] = pa[it].z; As[kv+3][r] = pa[it].w;
        }
#pragma unroll
        for (int it = 0; it < 4; ++it) {
            int li = tid + it * 256;
            int kk = li >> 5;
            int nv = (li & 31) << 2;
            *(float4*)&Bs[kk][nv] = *(const float4*)(Bw + (size_t)(k0 + kk) * CC + nv);
        }
        __syncthreads();
        if (cc + 1 < chunks) {
            const int kn = k0 + 32;
#pragma unroll
            for (int it = 0; it < 4; ++it) {
                int li = tid + it * 256;
                int gm = m0 + (li >> 3);
                pa[it] = make_float4(0.f,0.f,0.f,0.f);
                if (gm < HW) pa[it] = *(const float4*)(A + (size_t)gm * K + kn + ((li & 7) << 2));
            }
        }
#pragma unroll
        for (int k = 0; k < 32; ++k) {
            float a[8], b[8];
            *(float4*)&a[0] = *(const float4*)&As[k][ty*8];
            *(float4*)&a[4] = *(const float4*)&As[k][ty*8+4];
            *(float4*)&b[0] = *(const float4*)&Bs[k][tx*8];
            *(float4*)&b[4] = *(const float4*)&Bs[k][tx*8+4];
#pragma unroll
            for (int i = 0; i < 8; ++i)
#pragma unroll
                for (int j = 0; j < 8; ++j)
                    acc[i][j] = fmaf(a[i], b[j], acc[i][j]);
        }
    }
    __syncthreads();
    // alias shared memory for LN reductions
    float* rs     = &As[0][0];        // 2048 floats
    float* rq     = rs + 2048;        // 2048 floats (As holds 4224)
    float* mean_s = &Bs[0][0];
    float* rstd_s = mean_s + 128;

#pragma unroll
    for (int i = 0; i < 8; ++i) {
        int row = m0 + ty*8 + i;
        float s = 0.f, qq = 0.f;
#pragma unroll
        for (int j = 0; j < 8; ++j) {
            int col = tx*8 + j;
            float v = acc[i][j] + bias[col] + ((row < HW) ? res[(size_t)row * CC + col] : 0.f);
            acc[i][j] = v;
            s += v; qq += v * v;
        }
        rs[(ty*8 + i) * 16 + tx] = s;
        rq[(ty*8 + i) * 16 + tx] = qq;
    }
    __syncthreads();
    if (tid < 128) {
        float s = 0.f, qq = 0.f;
#pragma unroll
        for (int u = 0; u < 16; ++u) { s += rs[tid*16 + u]; qq += rq[tid*16 + u]; }
        float m = s * (1.0f / 128.0f);
        float v = qq * (1.0f / 128.0f) - m * m;
        mean_s[tid] = m;
        rstd_s[tid] = rsqrtf(v + 1e-5f);
    }
    __syncthreads();
#pragma unroll
    for (int i = 0; i < 8; ++i) {
        int row = m0 + ty*8 + i;
        if (row < HW) {
            float m = mean_s[ty*8 + i], rst = rstd_s[ty*8 + i];
#pragma unroll
            for (int j = 0; j < 8; ++j) {
                int col = tx*8 + j;
                out[(size_t)row * CC + col] = (acc[i][j] - m) * rst * gamma[col] + beta[col];
            }
        }
    }
}

// ---------------- FFN1: [HW x 128] @ [128 x 1024] + bias + relu ----------------
__global__ __launch_bounds__(256) void ffn1_kernel(const float* __restrict__ W1,
                                                   const float* __restrict__ b1) {
    __shared__ __align__(16) float As[32][132];
    __shared__ __align__(16) float Bs[32][132];
    const int m0 = blockIdx.x * 128;
    const int n0 = blockIdx.y * 128;
    const int tid = threadIdx.x;
    const int tx = tid & 15, ty = tid >> 4;
    float acc[8][8];
#pragma unroll
    for (int i = 0; i < 8; ++i)
#pragma unroll
        for (int j = 0; j < 8; ++j) acc[i][j] = 0.f;

    // A prefetch registers
    float4 pa[4];
#pragma unroll
    for (int it = 0; it < 4; ++it) {
        int li = tid + it * 256;
        int gm = m0 + (li >> 3);
        pa[it] = make_float4(0.f,0.f,0.f,0.f);
        if (gm < HW) pa[it] = *(const float4*)(g_src + (size_t)gm * CC + ((li & 7) << 2));
    }

    for (int cc = 0; cc < 4; ++cc) {
        const int k0 = cc * 32;
        __syncthreads();
#pragma unroll
        for (int it = 0; it < 4; ++it) {
            int li = tid + it * 256;
            int r  = li >> 3;
            int kv = (li & 7) << 2;
            As[kv+0][r] = pa[it].x; As[kv+1][r] = pa[it].y;
            As[kv+2][r] = pa[it].z; As[kv+3][r] = pa[it].w;
        }
#pragma unroll
        for (int it = 0; it < 4; ++it) {
            int li = tid + it * 256;
            int kk = li >> 5;
            int nv = (li & 31) << 2;
            *(float4*)&Bs[kk][nv] = *(const float4*)(W1 + (size_t)(k0 + kk) * DFF + n0 + nv);
        }
        __syncthreads();
        if (cc < 3) {
            const int kn = k0 + 32;
#pragma unroll
            for (int it = 0; it < 4; ++it) {
                int li = tid + it * 256;
                int gm = m0 + (li >> 3);
                pa[it] = make_float4(0.f,0.f,0.f,0.f);
                if (gm < HW) pa[it] = *(const float4*)(g_src + (size_t)gm * CC + kn + ((li & 7) << 2));
            }
        }
#pragma unroll
        for (int k = 0; k < 32; ++k) {
            float a[8], b[8];
            *(float4*)&a[0] = *(const float4*)&As[k][ty*8];
            *(float4*)&a[4] = *(const float4*)&As[k][ty*8+4];
            *(float4*)&b[0] = *(const float4*)&Bs[k][tx*8];
            *(float4*)&b[4] = *(const float4*)&Bs[k][tx*8+4];
#pragma unroll
            for (int i = 0; i < 8; ++i)
#pragma unroll
                for (int j = 0; j < 8; ++j)
                    acc[i][j] = fmaf(a[i], b[j], acc[i][j]);
        }
    }
#pragma unroll
    for (int i = 0; i < 8; ++i) {
        int row = m0 + ty*8 + i;
        if (row < HW) {
#pragma unroll
            for (int j = 0; j < 8; ++j) {
                int col = n0 + tx*8 + j;
                g_hidden[(size_t)row * DFF + col] = fmaxf(acc[i][j] + b1[col], 0.f);
            }
        }
    }
}

// ---------------- launch ----------------
extern "C" void kernel_launch(void* const* d_in, const int* in_sizes, int n_in,
                              void* d_out, int out_size) {
    const float* src_all  = (const float*)d_in[0];
    const float* refpts   = (const float*)d_in[1];
    // d_in[2] spatial_shape: constant 180x180, hardcoded
    const float* conv_w   = (const float*)d_in[3];
    const float* conv_b   = (const float*)d_in[4];
    const float* W_val    = (const float*)d_in[5];
    const float* b_val    = (const float*)d_in[6];
    const float* W_off    = (const float*)d_in[7];
    const float* b_off    = (const float*)d_in[8];
    const float* W_attn   = (const float*)d_in[9];
    const float* b_attn   = (const float*)d_in[10];
    const float* W_out    = (const float*)d_in[11];
    const float* b_out    = (const float*)d_in[12];
    const float* ln1_g    = (const float*)d_in[13];
    const float* ln1_b    = (const float*)d_in[14];
    const float* W1       = (const float*)d_in[15];
    const float* b1       = (const float*)d_in[16];
    const float* W2       = (const float*)d_in[17];
    const float* b2       = (const float*)d_in[18];
    const float* ln2_g    = (const float*)d_in[19];
    const float* ln2_b    = (const float*)d_in[20];
    float* outp = (float*)d_out;

    float *p_attnout, *p_src, *p_hidden;
    cudaGetSymbolAddress((void**)&p_attnout, g_attnout);
    cudaGetSymbolAddress((void**)&p_src, g_src);
    cudaGetSymbolAddress((void**)&p_hidden, g_hidden);

    const int MT = (HW + 127) / 128;       // 254
    const int MQT = (MQ + 127) / 128;      // 760

    wtrans_kernel<<<(9*256*128 + 255)/256, 256>>>(conv_w);
    conv_kernel<<<dim3(MT, LVL), 256>>>(src_all, conv_b);
    value_kernel<<<MQT, 256>>>(src_all, W_val, b_val);
    offattn_kernel<<<MQT, 256>>>(W_off, b_off, W_attn, b_attn);
    sample_kernel<<<HW/2, 256>>>(refpts);
    gemm_ln_kernel<<<MT, 256>>>(p_attnout, 128, W_out, b_out, src_all, ln1_g, ln1_b, p_src);
    ffn1_kernel<<<dim3(MT, DFF/128), 256>>>(W1, b1);
    gemm_ln_kernel<<<MT, 256>>>(p_hidden, DFF, W2, b2, p_src, ln2_g, ln2_b, outp);
}

// round 11
// speedup vs baseline: 1.5840x; 1.5840x over previous
#include <cuda_runtime.h>
#include <cuda_bf16.h>
#include <mma.h>
#include <math.h>
#include <stdint.h>

using namespace nvcuda;

#define LVL 3
#define HH 180
#define WIW 180
#define HW 32400
#define CC 128
#define HEADS 8
#define PP 4
#define DFF 1024
#define MQ (LVL*HW)           // 97200

// ---------------- scratch (device globals; no allocation allowed) ----------------
__device__ float g_queries[(size_t)LVL*HW*CC];    // [l][p][c]
__device__ float g_value[(size_t)LVL*HW*CC];      // [l][h][p][dh]
__device__ float g_offattn[(size_t)LVL*HW*96];    // [l][p][64 off | 32 logits]
__device__ float g_attnout[(size_t)HW*CC];        // [p][c]
__device__ float g_src[(size_t)HW*CC];            // after LN1
__device__ float g_hidden[(size_t)HW*DFF];        // FFN hidden
// bf16 split operands for the WMMA conv
__device__ __nv_bfloat16 g_src_hi[(size_t)LVL*HW*CC];
__device__ __nv_bfloat16 g_src_lo[(size_t)LVL*HW*CC];
__device__ __nv_bfloat16 g_wbf_hi[9*256*128];     // [tap][ci][co]  (B row-major KxN)
__device__ __nv_bfloat16 g_wbf_lo[9*256*128];

// ---------------- prep: split src (fp32 -> bf16 hi/lo) ----------------
__global__ void split_src_kernel(const float* __restrict__ src) {
    size_t i = (size_t)blockIdx.x * 256 + threadIdx.x;
    if (i >= (size_t)LVL*HW*CC) return;
    float v = src[i];
    __nv_bfloat16 hi = __float2bfloat16(v);
    __nv_bfloat16 lo = __float2bfloat16(v - __bfloat162float(hi));
    g_src_hi[i] = hi;
    g_src_lo[i] = lo;
}

// ---------------- prep: split conv weights -> [tap][ci][co] bf16 hi/lo ----------------
__global__ void wsplit_kernel(const float* __restrict__ conv_w) {
    int idx = blockIdx.x * 256 + threadIdx.x;
    if (idx >= 9*256*128) return;
    int o = idx & 127;
    int i = (idx >> 7) & 255;
    int t = idx >> 15;
    float v = conv_w[(o*256 + i)*9 + t];
    __nv_bfloat16 hi = __float2bfloat16(v);
    __nv_bfloat16 lo = __float2bfloat16(v - __bfloat162float(hi));
    g_wbf_hi[idx] = hi;   // layout: [t][i][o]
    g_wbf_lo[idx] = lo;
}

// ---------------- conv via WMMA bf16 split: per CTA one 128x128 output tile ----------------
// K = 9 taps x 256 ci = 72 chunks of 32. D += Ahi*Bhi + Ahi*Blo + Alo*Bhi (fp32 acc).
// SMEM (bytes): A tiles 128x(32+8pad) bf16 hi/lo, B tiles 32x(128+8pad) bf16 hi/lo;
// fp32 stage 128x132 aliases the operand region after the mainloop.
#define CV_AHI  0
#define CV_ALO  10240
#define CV_BHI  20480
#define CV_BLO  29184
#define CV_SMEM 67584          // stage: 128*132*4

__global__ __launch_bounds__(256) void conv_wmma_kernel(const float* __restrict__ conv_b) {
    extern __shared__ char smem[];
    const int tid = threadIdx.x;
    const int wid = tid >> 5;
    const int l  = blockIdx.y;
    const int m0 = blockIdx.x * 128;
    const int wm = wid & 1;        // 0..1  (M groups of 64)
    const int wn = wid >> 1;       // 0..3  (N groups of 32)

    wmma::fragment<wmma::accumulator, 16, 16, 16, float> acc[4][2];
#pragma unroll
    for (int i = 0; i < 4; ++i)
#pragma unroll
        for (int j = 0; j < 2; ++j) wmma::fill_fragment(acc[i][j], 0.f);

    // A-gather jobs: 128 rows x 4 segs (8 bf16 each) = 512 jobs -> 2 per thread
    const int segA = tid & 3;
    int rr_[2]; bool rv_[2]; int ry_[2], rx_[2];
#pragma unroll
    for (int k2 = 0; k2 < 2; ++k2) {
        rr_[k2] = (tid >> 2) + k2 * 64;
        int gm = m0 + rr_[k2];
        rv_[k2] = (gm < HW);
        int gmc = rv_[k2] ? gm : 0;
        ry_[k2] = gmc / WIW;
        rx_[k2] = gmc % WIW;
    }
    // B-copy jobs: 32 rows x 16 segs = 512 jobs -> 2 per thread
    const int segB = tid & 15;
    const int rb0  = tid >> 4;

    const uint4 zz = make_uint4(0u,0u,0u,0u);

    for (int u = 0; u < 72; ++u) {
        const int t  = u >> 3;
        const int c0 = (u & 7) * 32;
        const int dy = t / 3 - 1, dx = t % 3 - 1;
        const int lsel = (c0 < 128) ? 0 : l;
        const int ch0  = c0 & 127;
        __syncthreads();   // previous chunk's reads complete
        // A tiles (hi/lo), shifted predicated gather
#pragma unroll
        for (int k2 = 0; k2 < 2; ++k2) {
            int row = rr_[k2];
            int y = ry_[k2] + dy, x = rx_[k2] + dx;
            bool v = rv_[k2] && y >= 0 && y < HH && x >= 0 && x < WIW;
            int pix = v ? (y * WIW + x) : 0;
            size_t go = (size_t)(lsel * HW + pix) * CC + ch0 + segA * 8;
            uint4 vh = v ? *(const uint4*)(g_src_hi + go) : zz;
            uint4 vl = v ? *(const uint4*)(g_src_lo + go) : zz;
            *(uint4*)(smem + CV_AHI + row*80 + segA*16) = vh;
            *(uint4*)(smem + CV_ALO + row*80 + segA*16) = vl;
        }
        // B tiles (hi/lo): rows ci0..ci0+31 of [t][ci][co]
#pragma unroll
        for (int k2 = 0; k2 < 2; ++k2) {
            int row = rb0 + k2 * 16;
            size_t go = (size_t)(t * 256 + c0 + row) * 128 + segB * 8;
            *(uint4*)(smem + CV_BHI + row*272 + segB*16) = *(const uint4*)(g_wbf_hi + go);
            *(uint4*)(smem + CV_BLO + row*272 + segB*16) = *(const uint4*)(g_wbf_lo + go);
        }
        __syncthreads();

        const __nv_bfloat16* As_hi = (const __nv_bfloat16*)(smem + CV_AHI);
        const __nv_bfloat16* As_lo = (const __nv_bfloat16*)(smem + CV_ALO);
        const __nv_bfloat16* Bs_hi = (const __nv_bfloat16*)(smem + CV_BHI);
        const __nv_bfloat16* Bs_lo = (const __nv_bfloat16*)(smem + CV_BLO);

#pragma unroll
        for (int ks = 0; ks < 2; ++ks) {
            wmma::fragment<wmma::matrix_b, 16, 16, 16, __nv_bfloat16, wmma::row_major> bh[2], bl[2];
#pragma unroll
            for (int j = 0; j < 2; ++j) {
                const __nv_bfloat16* bp = Bs_hi + (ks*16)*136 + wn*32 + j*16;
                wmma::load_matrix_sync(bh[j], bp, 136);
                const __nv_bfloat16* bq = Bs_lo + (ks*16)*136 + wn*32 + j*16;
                wmma::load_matrix_sync(bl[j], bq, 136);
            }
#pragma unroll
            for (int i = 0; i < 4; ++i) {
                wmma::fragment<wmma::matrix_a, 16, 16, 16, __nv_bfloat16, wmma::row_major> ah, al;
                wmma::load_matrix_sync(ah, As_hi + (wm*64 + i*16)*40 + ks*16, 40);
                wmma::load_matrix_sync(al, As_lo + (wm*64 + i*16)*40 + ks*16, 40);
#pragma unroll
                for (int j = 0; j < 2; ++j) {
                    wmma::mma_sync(acc[i][j], ah, bh[j], acc[i][j]);
                    wmma::mma_sync(acc[i][j], ah, bl[j], acc[i][j]);
                    wmma::mma_sync(acc[i][j], al, bh[j], acc[i][j]);
                }
            }
        }
    }
    __syncthreads();                      // operands dead; alias stage over them
    float* stage = (float*)smem;
#pragma unroll
    for (int i = 0; i < 4; ++i)
#pragma unroll
        for (int j = 0; j < 2; ++j)
            wmma::store_matrix_sync(stage + (wm*64 + i*16)*132 + wn*32 + j*16,
                                    acc[i][j], 132, wmma::mem_row_major);
    __syncthreads();

    float* outp = g_queries + (size_t)l * HW * CC;
    for (int idx = tid; idx < 128*32; idx += 256) {
        int row = idx >> 5, sg = idx & 31;
        int grow = m0 + row;
        if (grow < HW) {
            float4 vv = *(float4*)(stage + row*132 + sg*4);
            float4 bb = *(const float4*)(conv_b + sg*4);
            vv.x += bb.x; vv.y += bb.y; vv.z += bb.z; vv.w += bb.w;
            *(float4*)(outp + (size_t)grow * CC + sg*4) = vv;
        }
    }
}

// ---------------- value projection: [MQ x 128] @ [128 x 128], store [l][h][p][dh] ----------------
__global__ __launch_bounds__(256) void value_kernel(const float* __restrict__ src,
                                                    const float* __restrict__ Wv,
                                                    const float* __restrict__ bv) {
    __shared__ __align__(16) float As[32][132];
    __shared__ __align__(16) float Bs[32][132];
    const int m0 = blockIdx.x * 128;
    const int tid = threadIdx.x;
    const int tx = tid & 15, ty = tid >> 4;
    float acc[8][8];
#pragma unroll
    for (int i = 0; i < 8; ++i)
#pragma unroll
        for (int j = 0; j < 8; ++j) acc[i][j] = 0.f;

    float4 pa[4];
#pragma unroll
    for (int it = 0; it < 4; ++it) {
        int li = tid + it * 256;
        int gm = m0 + (li >> 3);
        pa[it] = make_float4(0.f,0.f,0.f,0.f);
        if (gm < MQ) pa[it] = *(const float4*)(src + (size_t)gm * CC + ((li & 7) << 2));
    }

    for (int cc = 0; cc < 4; ++cc) {
        const int k0 = cc * 32;
        __syncthreads();
#pragma unroll
        for (int it = 0; it < 4; ++it) {
            int li = tid + it * 256;
            int r  = li >> 3;
            int kv = (li & 7) << 2;
            As[kv+0][r] = pa[it].x; As[kv+1][r] = pa[it].y;
            As[kv+2][r] = pa[it].z; As[kv+3][r] = pa[it].w;
        }
#pragma unroll
        for (int it = 0; it < 4; ++it) {
            int li = tid + it * 256;
            int kk = li >> 5;
            int nv = (li & 31) << 2;
            *(float4*)&Bs[kk][nv] = *(const float4*)(Wv + (size_t)(k0 + kk) * CC + nv);
        }
        __syncthreads();
        if (cc < 3) {
            const int kn = k0 + 32;
#pragma unroll
            for (int it = 0; it < 4; ++it) {
                int li = tid + it * 256;
                int gm = m0 + (li >> 3);
                pa[it] = make_float4(0.f,0.f,0.f,0.f);
                if (gm < MQ) pa[it] = *(const float4*)(src + (size_t)gm * CC + kn + ((li & 7) << 2));
            }
        }
#pragma unroll
        for (int k = 0; k < 32; ++k) {
            float a[8], b[8];
            *(float4*)&a[0] = *(const float4*)&As[k][ty*8];
            *(float4*)&a[4] = *(const float4*)&As[k][ty*8+4];
            *(float4*)&b[0] = *(const float4*)&Bs[k][tx*8];
            *(float4*)&b[4] = *(const float4*)&Bs[k][tx*8+4];
#pragma unroll
            for (int i = 0; i < 8; ++i)
#pragma unroll
                for (int j = 0; j < 8; ++j)
                    acc[i][j] = fmaf(a[i], b[j], acc[i][j]);
        }
    }
#pragma unroll
    for (int i = 0; i < 8; ++i) {
        int row = m0 + ty*8 + i;
        if (row < MQ) {
            int l = row / HW;
            int p = row - l * HW;
#pragma unroll
            for (int j = 0; j < 8; ++j) {
                int col = tx*8 + j;
                int h = col >> 4, dd = col & 15;
                g_value[((size_t)(l*8 + h) * HW + p) * 16 + dd] = acc[i][j] + bv[col];
            }
        }
    }
}

// ---------------- offsets + attn logits: [MQ x 128] @ [128 x 96] ----------------
__global__ __launch_bounds__(256) void offattn_kernel(const float* __restrict__ W_off,
                                                      const float* __restrict__ b_off,
                                                      const float* __restrict__ W_attn,
                                                      const float* __restrict__ b_attn) {
    __shared__ __align__(16) float As[32][132];
    __shared__ __align__(16) float Bs[32][96];
    const int m0 = blockIdx.x * 128;
    const int tid = threadIdx.x;
    const int tx = tid & 15, ty = tid >> 4;
    float acc[8][6];
#pragma unroll
    for (int i = 0; i < 8; ++i)
#pragma unroll
        for (int j = 0; j < 6; ++j) acc[i][j] = 0.f;

    float4 pa[4];
#pragma unroll
    for (int it = 0; it < 4; ++it) {
        int li = tid + it * 256;
        int gm = m0 + (li >> 3);
        pa[it] = make_float4(0.f,0.f,0.f,0.f);
        if (gm < MQ) pa[it] = *(const float4*)(g_queries + (size_t)gm * CC + ((li & 7) << 2));
    }

    for (int cc = 0; cc < 4; ++cc) {
        const int k0 = cc * 32;
        __syncthreads();
#pragma unroll
        for (int it = 0; it < 4; ++it) {
            int li = tid + it * 256;
            int r  = li >> 3;
            int kv = (li & 7) << 2;
            As[kv+0][r] = pa[it].x; As[kv+1][r] = pa[it].y;
            As[kv+2][r] = pa[it].z; As[kv+3][r] = pa[it].w;
        }
#pragma unroll
        for (int it = 0; it < 3; ++it) {
            int li = tid + it * 256;   // 0..767 = 32*24
            int kk = li / 24;
            int nv = (li % 24) << 2;
            float4 v;
            if (nv < 64) v = *(const float4*)(W_off  + (size_t)(k0 + kk) * 64 + nv);
            else         v = *(const float4*)(W_attn + (size_t)(k0 + kk) * 32 + (nv - 64));
            *(float4*)&Bs[kk][nv] = v;
        }
        __syncthreads();
        if (cc < 3) {
            const int kn = k0 + 32;
#pragma unroll
            for (int it = 0; it < 4; ++it) {
                int li = tid + it * 256;
                int gm = m0 + (li >> 3);
                pa[it] = make_float4(0.f,0.f,0.f,0.f);
                if (gm < MQ) pa[it] = *(const float4*)(g_queries + (size_t)gm * CC + kn + ((li & 7) << 2));
            }
        }
#pragma unroll
        for (int k = 0; k < 32; ++k) {
            float a[8];
            *(float4*)&a[0] = *(const float4*)&As[k][ty*8];
            *(float4*)&a[4] = *(const float4*)&As[k][ty*8+4];
            float b[6];
#pragma unroll
            for (int j = 0; j < 6; ++j) b[j] = Bs[k][tx*6 + j];
#pragma unroll
            for (int i = 0; i < 8; ++i)
#pragma unroll
                for (int j = 0; j < 6; ++j)
                    acc[i][j] = fmaf(a[i], b[j], acc[i][j]);
        }
    }
#pragma unroll
    for (int i = 0; i < 8; ++i) {
        int row = m0 + ty*8 + i;
        if (row < MQ) {
#pragma unroll
            for (int j = 0; j < 6; ++j) {
                int col = tx*6 + j;
                float bias = (col < 64) ? b_off[col] : b_attn[col - 64];
                g_offattn[(size_t)row * 96 + col] = acc[i][j] + bias;
            }
        }
    }
}

// ---------------- deformable sampling + softmax + weighted sum (2 queries/block) ----------------
__global__ __launch_bounds__(256) void sample_kernel(const float* __restrict__ refpts) {
    __shared__ float oa[2][3][96];
    __shared__ float rp[2][6];
    const int q0 = blockIdx.x * 2;
    const int tid = threadIdx.x;
    const int sq = tid >> 7;
    const int t  = tid & 127;
    const int q  = q0 + sq;

    for (int i = tid; i < 2*288; i += 256) {
        int qq = i / 288;
        int rem = i - qq * 288;
        int l = rem / 96, j = rem - l * 96;
        oa[qq][l][j] = g_offattn[((size_t)l * HW + q0 + qq) * 96 + j];
    }
    if (tid < 12) rp[tid / 6][tid % 6] = refpts[(size_t)q0 * 6 + tid];
    __syncthreads();

    const int h = t >> 4, d = t & 15;
    float mx = -1e30f;
#pragma unroll
    for (int l = 0; l < 3; ++l)
#pragma unroll
        for (int p = 0; p < 4; ++p) mx = fmaxf(mx, oa[sq][l][64 + h*4 + p]);
    float den = 0.f;
#pragma unroll
    for (int l = 0; l < 3; ++l)
#pragma unroll
        for (int p = 0; p < 4; ++p) den += expf(oa[sq][l][64 + h*4 + p] - mx);
    const float inv = 1.0f / den;

    float acc = 0.f;
#pragma unroll
    for (int l = 0; l < 3; ++l) {
        const float rx = rp[sq][l*2 + 0], ry = rp[sq][l*2 + 1];
        const float* vb = g_value + (size_t)(l*8 + h) * HW * 16 + d;

        float w00[4], w01[4], w10[4], w11[4], aw[4];
        int o00[4], o01[4], o10[4], o11[4];
#pragma unroll
        for (int p = 0; p < 4; ++p) {
            float ox = oa[sq][l][h*8 + p*2 + 0];
            float oy = oa[sq][l][h*8 + p*2 + 1];
            aw[p] = expf(oa[sq][l][64 + h*4 + p] - mx) * inv;
            float px = (rx + ox * (1.0f/180.0f)) * 180.0f - 0.5f;
            float py = (ry + oy * (1.0f/180.0f)) * 180.0f - 0.5f;
            float xf = floorf(px), yf = floorf(py);
            int x0 = (int)xf, y0 = (int)yf;
            float fx = px - xf, fy = py - yf;
            float vx0 = (x0   >= 0 && x0   < WIW) ? 1.f : 0.f;
            float vx1 = (x0+1 >= 0 && x0+1 < WIW) ? 1.f : 0.f;
            float vy0 = (y0   >= 0 && y0   < HH)  ? 1.f : 0.f;
            float vy1 = (y0+1 >= 0 && y0+1 < HH)  ? 1.f : 0.f;
            int cx0 = min(max(x0,     0), WIW-1);
            int cx1 = min(max(x0 + 1, 0), WIW-1);
            int cy0 = min(max(y0,     0), HH-1);
            int cy1 = min(max(y0 + 1, 0), HH-1);
            w00[p] = (1.f-fx)*(1.f-fy) * vx0 * vy0;
            w01[p] = fx      *(1.f-fy) * vx1 * vy0;
            w10[p] = (1.f-fx)*fy       * vx0 * vy1;
            w11[p] = fx      *fy       * vx1 * vy1;
            o00[p] = (cy0 * WIW + cx0) * 16;
            o01[p] = (cy0 * WIW + cx1) * 16;
            o10[p] = (cy1 * WIW + cx0) * 16;
            o11[p] = (cy1 * WIW + cx1) * 16;
        }

        float g00[4], g01[4], g10[4], g11[4];
#pragma unroll
        for (int p = 0; p < 4; ++p) {
            g00[p] = vb[o00[p]];
            g01[p] = vb[o01[p]];
            g10[p] = vb[o10[p]];
            g11[p] = vb[o11[p]];
        }
#pragma unroll
        for (int p = 0; p < 4; ++p) {
            float s = w00[p]*g00[p] + w01[p]*g01[p] + w10[p]*g10[p] + w11[p]*g11[p];
            acc = fmaf(aw[p], s, acc);
        }
    }
    g_attnout[(size_t)q * CC + t] = acc;
}

// ---------------- GEMM (M=HW, N=128, K param) + bias + residual + LayerNorm ----------------
__global__ __launch_bounds__(256) void gemm_ln_kernel(const float* __restrict__ A, int K,
                                                      const float* __restrict__ Bw,
                                                      const float* __restrict__ bias,
                                                      const float* __restrict__ res,
                                                      const float* __restrict__ gamma,
                                                      const float* __restrict__ beta,
                                                      float* __restrict__ out) {
    __shared__ __align__(16) float As[32][132];
    __shared__ __align__(16) float Bs[32][132];
    const int m0 = blockIdx.x * 128;
    const int tid = threadIdx.x;
    const int tx = tid & 15, ty = tid >> 4;
    float acc[8][8];
#pragma unroll
    for (int i = 0; i < 8; ++i)
#pragma unroll
        for (int j = 0; j < 8; ++j) acc[i][j] = 0.f;

    const int chunks = K >> 5;

    float4 pa[4];
#pragma unroll
    for (int it = 0; it < 4; ++it) {
        int li = tid + it * 256;
        int gm = m0 + (li >> 3);
        pa[it] = make_float4(0.f,0.f,0.f,0.f);
        if (gm < HW) pa[it] = *(const float4*)(A + (size_t)gm * K + ((li & 7) << 2));
    }

    for (int cc = 0; cc < chunks; ++cc) {
        const int k0 = cc * 32;
        __syncthreads();
#pragma unroll
        for (int it = 0; it < 4; ++it) {
            int li = tid + it * 256;
            int r  = li >> 3;
            int kv = (li & 7) << 2;
            As[kv+0][r] = pa[it].x; As[kv+1][r] = pa[it].y;
            As[kv+2][r] = pa[it].z; As[kv+3][r] = pa[it].w;
        }
#pragma unroll
        for (int it = 0; it < 4; ++it) {
            int li = tid + it * 256;
            int kk = li >> 5;
            int nv = (li & 31) << 2;
            *(float4*)&Bs[kk][nv] = *(const float4*)(Bw + (size_t)(k0 + kk) * CC + nv);
        }
        __syncthreads();
        if (cc + 1 < chunks) {
            const int kn = k0 + 32;
#pragma unroll
            for (int it = 0; it < 4; ++it) {
                int li = tid + it * 256;
                int gm = m0 + (li >> 3);
                pa[it] = make_float4(0.f,0.f,0.f,0.f);
                if (gm < HW) pa[it] = *(const float4*)(A + (size_t)gm * K + kn + ((li & 7) << 2));
            }
        }
#pragma unroll
        for (int k = 0; k < 32; ++k) {
            float a[8], b[8];
            *(float4*)&a[0] = *(const float4*)&As[k][ty*8];
            *(float4*)&a[4] = *(const float4*)&As[k][ty*8+4];
            *(float4*)&b[0] = *(const float4*)&Bs[k][tx*8];
            *(float4*)&b[4] = *(const float4*)&Bs[k][tx*8+4];
#pragma unroll
            for (int i = 0; i < 8; ++i)
#pragma unroll
                for (int j = 0; j < 8; ++j)
                    acc[i][j] = fmaf(a[i], b[j], acc[i][j]);
        }
    }
    __syncthreads();
    float* rs     = &As[0][0];
    float* rq     = rs + 2048;
    float* mean_s = &Bs[0][0];
    float* rstd_s = mean_s + 128;

#pragma unroll
    for (int i = 0; i < 8; ++i) {
        int row = m0 + ty*8 + i;
        float s = 0.f, qq = 0.f;
#pragma unroll
        for (int j = 0; j < 8; ++j) {
            int col = tx*8 + j;
            float v = acc[i][j] + bias[col] + ((row < HW) ? res[(size_t)row * CC + col] : 0.f);
            acc[i][j] = v;
            s += v; qq += v * v;
        }
        rs[(ty*8 + i) * 16 + tx] = s;
        rq[(ty*8 + i) * 16 + tx] = qq;
    }
    __syncthreads();
    if (tid < 128) {
        float s = 0.f, qq = 0.f;
#pragma unroll
        for (int u = 0; u < 16; ++u) { s += rs[tid*16 + u]; qq += rq[tid*16 + u]; }
        float m = s * (1.0f / 128.0f);
        float v = qq * (1.0f / 128.0f) - m * m;
        mean_s[tid] = m;
        rstd_s[tid] = rsqrtf(v + 1e-5f);
    }
    __syncthreads();
#pragma unroll
    for (int i = 0; i < 8; ++i) {
        int row = m0 + ty*8 + i;
        if (row < HW) {
            float m = mean_s[ty*8 + i], rst = rstd_s[ty*8 + i];
#pragma unroll
            for (int j = 0; j < 8; ++j) {
                int col = tx*8 + j;
                out[(size_t)row * CC + col] = (acc[i][j] - m) * rst * gamma[col] + beta[col];
            }
        }
    }
}

// ---------------- FFN1: [HW x 128] @ [128 x 1024] + bias + relu ----------------
__global__ __launch_bounds__(256) void ffn1_kernel(const float* __restrict__ W1,
                                                   const float* __restrict__ b1) {
    __shared__ __align__(16) float As[32][132];
    __shared__ __align__(16) float Bs[32][132];
    const int m0 = blockIdx.x * 128;
    const int n0 = blockIdx.y * 128;
    const int tid = threadIdx.x;
    const int tx = tid & 15, ty = tid >> 4;
    float acc[8][8];
#pragma unroll
    for (int i = 0; i < 8; ++i)
#pragma unroll
        for (int j = 0; j < 8; ++j) acc[i][j] = 0.f;

    float4 pa[4];
#pragma unroll
    for (int it = 0; it < 4; ++it) {
        int li = tid + it * 256;
        int gm = m0 + (li >> 3);
        pa[it] = make_float4(0.f,0.f,0.f,0.f);
        if (gm < HW) pa[it] = *(const float4*)(g_src + (size_t)gm * CC + ((li & 7) << 2));
    }

    for (int cc = 0; cc < 4; ++cc) {
        const int k0 = cc * 32;
        __syncthreads();
#pragma unroll
        for (int it = 0; it < 4; ++it) {
            int li = tid + it * 256;
            int r  = li >> 3;
            int kv = (li & 7) << 2;
            As[kv+0][r] = pa[it].x; As[kv+1][r] = pa[it].y;
            As[kv+2][r] = pa[it].z; As[kv+3][r] = pa[it].w;
        }
#pragma unroll
        for (int it = 0; it < 4; ++it) {
            int li = tid + it * 256;
            int kk = li >> 5;
            int nv = (li & 31) << 2;
            *(float4*)&Bs[kk][nv] = *(const float4*)(W1 + (size_t)(k0 + kk) * DFF + n0 + nv);
        }
        __syncthreads();
        if (cc < 3) {
            const int kn = k0 + 32;
#pragma unroll
            for (int it = 0; it < 4; ++it) {
                int li = tid + it * 256;
                int gm = m0 + (li >> 3);
                pa[it] = make_float4(0.f,0.f,0.f,0.f);
                if (gm < HW) pa[it] = *(const float4*)(g_src + (size_t)gm * CC + kn + ((li & 7) << 2));
            }
        }
#pragma unroll
        for (int k = 0; k < 32; ++k) {
            float a[8], b[8];
            *(float4*)&a[0] = *(const float4*)&As[k][ty*8];
            *(float4*)&a[4] = *(const float4*)&As[k][ty*8+4];
            *(float4*)&b[0] = *(const float4*)&Bs[k][tx*8];
            *(float4*)&b[4] = *(const float4*)&Bs[k][tx*8+4];
#pragma unroll
            for (int i = 0; i < 8; ++i)
#pragma unroll
                for (int j = 0; j < 8; ++j)
                    acc[i][j] = fmaf(a[i], b[j], acc[i][j]);
        }
    }
#pragma unroll
    for (int i = 0; i < 8; ++i) {
        int row = m0 + ty*8 + i;
        if (row < HW) {
#pragma unroll
            for (int j = 0; j < 8; ++j) {
                int col = n0 + tx*8 + j;
                g_hidden[(size_t)row * DFF + col] = fmaxf(acc[i][j] + b1[col], 0.f);
            }
        }
    }
}

// ---------------- launch ----------------
extern "C" void kernel_launch(void* const* d_in, const int* in_sizes, int n_in,
                              void* d_out, int out_size) {
    const float* src_all  = (const float*)d_in[0];
    const float* refpts   = (const float*)d_in[1];
    const float* conv_w   = (const float*)d_in[3];
    const float* conv_b   = (const float*)d_in[4];
    const float* W_val    = (const float*)d_in[5];
    const float* b_val    = (const float*)d_in[6];
    const float* W_off    = (const float*)d_in[7];
    const float* b_off    = (const float*)d_in[8];
    const float* W_attn   = (const float*)d_in[9];
    const float* b_attn   = (const float*)d_in[10];
    const float* W_out    = (const float*)d_in[11];
    const float* b_out    = (const float*)d_in[12];
    const float* ln1_g    = (const float*)d_in[13];
    const float* ln1_b    = (const float*)d_in[14];
    const float* W1       = (const float*)d_in[15];
    const float* b1       = (const float*)d_in[16];
    const float* W2       = (const float*)d_in[17];
    const float* b2       = (const float*)d_in[18];
    const float* ln2_g    = (const float*)d_in[19];
    const float* ln2_b    = (const float*)d_in[20];
    float* outp = (float*)d_out;

    float *p_attnout, *p_src, *p_hidden;
    cudaGetSymbolAddress((void**)&p_attnout, g_attnout);
    cudaGetSymbolAddress((void**)&p_src, g_src);
    cudaGetSymbolAddress((void**)&p_hidden, g_hidden);

    cudaFuncSetAttribute(conv_wmma_kernel, cudaFuncAttributeMaxDynamicSharedMemorySize, CV_SMEM);

    const int MT  = (HW + 127) / 128;      // 254
    const int MQT = (MQ + 127) / 128;      // 760
    const size_t NSRC = (size_t)LVL*HW*CC; // 12.44M

    split_src_kernel<<<(unsigned)((NSRC + 255) / 256), 256>>>(src_all);
    wsplit_kernel<<<(9*256*128 + 255)/256, 256>>>(conv_w);
    conv_wmma_kernel<<<dim3(MT, LVL), 256, CV_SMEM>>>(conv_b);
    value_kernel<<<MQT, 256>>>(src_all, W_val, b_val);
    offattn_kernel<<<MQT, 256>>>(W_off, b_off, W_attn, b_attn);
    sample_kernel<<<HW/2, 256>>>(refpts);
    gemm_ln_kernel<<<MT, 256>>>(p_attnout, 128, W_out, b_out, src_all, ln1_g, ln1_b, p_src);
    ffn1_kernel<<<dim3(MT, DFF/128), 256>>>(W1, b1);
    gemm_ln_kernel<<<MT, 256>>>(p_hidden, DFF, W2, b2, p_src, ln2_g, ln2_b, outp);
}

// round 13
// speedup vs baseline: 1.9099x; 1.2057x over previous
#include <cuda_runtime.h>
#include <cuda_bf16.h>
#include <mma.h>
#include <math.h>
#include <stdint.h>

using namespace nvcuda;

#define LVL 3
#define HH 180
#define WIW 180
#define HW 32400
#define CC 128
#define HEADS 8
#define PP 4
#define DFF 1024
#define MQ (LVL*HW)           // 97200

// ---------------- scratch (device globals; no allocation allowed) ----------------
__device__ float g_queries[(size_t)LVL*HW*CC];    // [l][p][c]
__device__ float g_value[(size_t)LVL*HW*CC];      // [l][h][p][dh]
__device__ float g_offattn[(size_t)LVL*HW*96];    // [l][p][64 off | 32 logits]
__device__ float g_attnout[(size_t)HW*CC];        // [p][c]
__device__ float g_src[(size_t)HW*CC];            // after LN1 (fp32, residual for LN2)
// bf16 split operands
__device__ __nv_bfloat16 g_src_hi[(size_t)LVL*HW*CC];
__device__ __nv_bfloat16 g_src_lo[(size_t)LVL*HW*CC];
__device__ __nv_bfloat16 g_wbf_hi[9*256*128];     // conv weights [tap][ci][co]
__device__ __nv_bfloat16 g_wbf_lo[9*256*128];
__device__ __nv_bfloat16 g_wv_hi[128*128];        // W_val
__device__ __nv_bfloat16 g_wv_lo[128*128];
__device__ __nv_bfloat16 g_w1_hi[128*1024];       // W1
__device__ __nv_bfloat16 g_w1_lo[128*1024];
__device__ __nv_bfloat16 g_w2_hi[1024*128];       // W2
__device__ __nv_bfloat16 g_w2_lo[1024*128];
__device__ __nv_bfloat16 g_srcbf_hi[(size_t)HW*CC];   // LN1 output split
__device__ __nv_bfloat16 g_srcbf_lo[(size_t)HW*CC];
__device__ __nv_bfloat16 g_hid_hi[(size_t)HW*DFF];    // FFN hidden split
__device__ __nv_bfloat16 g_hid_lo[(size_t)HW*DFF];

// ---------------- prep: split src (fp32 -> bf16 hi/lo) ----------------
__global__ void split_src_kernel(const float* __restrict__ src) {
    size_t i = (size_t)blockIdx.x * 256 + threadIdx.x;
    if (i >= (size_t)LVL*HW*CC) return;
    float v = src[i];
    __nv_bfloat16 hi = __float2bfloat16(v);
    __nv_bfloat16 lo = __float2bfloat16(v - __bfloat162float(hi));
    g_src_hi[i] = hi;
    g_src_lo[i] = lo;
}

// ---------------- prep: split conv weights -> [tap][ci][co] bf16 hi/lo ----------------
__global__ void wsplit_kernel(const float* __restrict__ conv_w) {
    int idx = blockIdx.x * 256 + threadIdx.x;
    if (idx >= 9*256*128) return;
    int o = idx & 127;
    int i = (idx >> 7) & 255;
    int t = idx >> 15;
    float v = conv_w[(o*256 + i)*9 + t];
    __nv_bfloat16 hi = __float2bfloat16(v);
    __nv_bfloat16 lo = __float2bfloat16(v - __bfloat162float(hi));
    g_wbf_hi[idx] = hi;
    g_wbf_lo[idx] = lo;
}

// ---------------- prep: generic matrix split (row-major, same layout) ----------------
__global__ void wsplit_mat_kernel(const float* __restrict__ src,
                                  __nv_bfloat16* __restrict__ hi_out,
                                  __nv_bfloat16* __restrict__ lo_out, int n) {
    int i = blockIdx.x * 256 + threadIdx.x;
    if (i >= n) return;
    float v = src[i];
    __nv_bfloat16 hi = __float2bfloat16(v);
    __nv_bfloat16 lo = __float2bfloat16(v - __bfloat162float(hi));
    hi_out[i] = hi;
    lo_out[i] = lo;
}

// ---------------- shared WMMA tile geometry ----------------
#define CV_AHI  0
#define CV_ALO  10240
#define CV_BHI  20480
#define CV_BLO  29184
#define CV_SMEM 67584          // fp32 stage 128x132 aliases operands after mainloop

// dense mainloop: A [M x Astride] bf16 hi/lo rows m0..m0+127 (clamped to Mmax-1),
// B [K x Bstride] bf16 hi/lo cols n0..n0+127, kchunks chunks of K=32.
__device__ __forceinline__ void wmma_dense_loop(
    char* smem, int tid, int m0, int Mmax,
    const __nv_bfloat16* __restrict__ Ahi, const __nv_bfloat16* __restrict__ Alo, int Astride,
    const __nv_bfloat16* __restrict__ Bhi, const __nv_bfloat16* __restrict__ Blo, int Bstride, int n0,
    int kchunks,
    wmma::fragment<wmma::accumulator, 16, 16, 16, float> acc[4][2])
{
    const int wid = tid >> 5;
    const int wm = wid & 1, wn = wid >> 1;
    const int segA = tid & 3;
    const int ra0  = tid >> 2;
    const int segB = tid & 15;
    const int rb0  = tid >> 4;

    for (int u = 0; u < kchunks; ++u) {
        const int k0 = u * 32;
        __syncthreads();
#pragma unroll
        for (int k2 = 0; k2 < 2; ++k2) {
            int row = ra0 + k2 * 64;
            int gmr = m0 + row; if (gmr > Mmax - 1) gmr = Mmax - 1;
            size_t go = (size_t)gmr * Astride + k0 + segA * 8;
            *(uint4*)(smem + CV_AHI + row*80 + segA*16) = *(const uint4*)(Ahi + go);
            *(uint4*)(smem + CV_ALO + row*80 + segA*16) = *(const uint4*)(Alo + go);
        }
#pragma unroll
        for (int k2 = 0; k2 < 2; ++k2) {
            int row = rb0 + k2 * 16;
            size_t go = (size_t)(k0 + row) * Bstride + n0 + segB * 8;
            *(uint4*)(smem + CV_BHI + row*272 + segB*16) = *(const uint4*)(Bhi + go);
            *(uint4*)(smem + CV_BLO + row*272 + segB*16) = *(const uint4*)(Blo + go);
        }
        __syncthreads();

        const __nv_bfloat16* As_hi = (const __nv_bfloat16*)(smem + CV_AHI);
        const __nv_bfloat16* As_lo = (const __nv_bfloat16*)(smem + CV_ALO);
        const __nv_bfloat16* Bs_hi = (const __nv_bfloat16*)(smem + CV_BHI);
        const __nv_bfloat16* Bs_lo = (const __nv_bfloat16*)(smem + CV_BLO);

#pragma unroll
        for (int ks = 0; ks < 2; ++ks) {
            wmma::fragment<wmma::matrix_b, 16, 16, 16, __nv_bfloat16, wmma::row_major> bh[2], bl[2];
#pragma unroll
            for (int j = 0; j < 2; ++j) {
                wmma::load_matrix_sync(bh[j], Bs_hi + (ks*16)*136 + wn*32 + j*16, 136);
                wmma::load_matrix_sync(bl[j], Bs_lo + (ks*16)*136 + wn*32 + j*16, 136);
            }
#pragma unroll
            for (int i = 0; i < 4; ++i) {
                wmma::fragment<wmma::matrix_a, 16, 16, 16, __nv_bfloat16, wmma::row_major> ah, al;
                wmma::load_matrix_sync(ah, As_hi + (wm*64 + i*16)*40 + ks*16, 40);
                wmma::load_matrix_sync(al, As_lo + (wm*64 + i*16)*40 + ks*16, 40);
#pragma unroll
                for (int j = 0; j < 2; ++j) {
                    wmma::mma_sync(acc[i][j], ah, bh[j], acc[i][j]);
                    wmma::mma_sync(acc[i][j], ah, bl[j], acc[i][j]);
                    wmma::mma_sync(acc[i][j], al, bh[j], acc[i][j]);
                }
            }
        }
    }
}

__device__ __forceinline__ void wmma_stage(
    char* smem, int tid,
    wmma::fragment<wmma::accumulator, 16, 16, 16, float> acc[4][2])
{
    const int wid = tid >> 5;
    const int wm = wid & 1, wn = wid >> 1;
    __syncthreads();
    float* stage = (float*)smem;
#pragma unroll
    for (int i = 0; i < 4; ++i)
#pragma unroll
        for (int j = 0; j < 2; ++j)
            wmma::store_matrix_sync(stage + (wm*64 + i*16)*132 + wn*32 + j*16,
                                    acc[i][j], 132, wmma::mem_row_major);
    __syncthreads();
}

// ---------------- conv via WMMA bf16 split (unchanged from passing R11 kernel) ----------------
__global__ __launch_bounds__(256) void conv_wmma_kernel(const float* __restrict__ conv_b) {
    extern __shared__ char smem[];
    const int tid = threadIdx.x;
    const int wid = tid >> 5;
    const int l  = blockIdx.y;
    const int m0 = blockIdx.x * 128;
    const int wm = wid & 1;
    const int wn = wid >> 1;

    wmma::fragment<wmma::accumulator, 16, 16, 16, float> acc[4][2];
#pragma unroll
    for (int i = 0; i < 4; ++i)
#pragma unroll
        for (int j = 0; j < 2; ++j) wmma::fill_fragment(acc[i][j], 0.f);

    const int segA = tid & 3;
    int rr_[2]; bool rv_[2]; int ry_[2], rx_[2];
#pragma unroll
    for (int k2 = 0; k2 < 2; ++k2) {
        rr_[k2] = (tid >> 2) + k2 * 64;
        int gm = m0 + rr_[k2];
        rv_[k2] = (gm < HW);
        int gmc = rv_[k2] ? gm : 0;
        ry_[k2] = gmc / WIW;
        rx_[k2] = gmc % WIW;
    }
    const int segB = tid & 15;
    const int rb0  = tid >> 4;
    const uint4 zz = make_uint4(0u,0u,0u,0u);

    for (int u = 0; u < 72; ++u) {
        const int t  = u >> 3;
        const int c0 = (u & 7) * 32;
        const int dy = t / 3 - 1, dx = t % 3 - 1;
        const int lsel = (c0 < 128) ? 0 : l;
        const int ch0  = c0 & 127;
        __syncthreads();
#pragma unroll
        for (int k2 = 0; k2 < 2; ++k2) {
            int row = rr_[k2];
            int y = ry_[k2] + dy, x = rx_[k2] + dx;
            bool v = rv_[k2] && y >= 0 && y < HH && x >= 0 && x < WIW;
            int pix = v ? (y * WIW + x) : 0;
            size_t go = (size_t)(lsel * HW + pix) * CC + ch0 + segA * 8;
            uint4 vh = v ? *(const uint4*)(g_src_hi + go) : zz;
            uint4 vl = v ? *(const uint4*)(g_src_lo + go) : zz;
            *(uint4*)(smem + CV_AHI + row*80 + segA*16) = vh;
            *(uint4*)(smem + CV_ALO + row*80 + segA*16) = vl;
        }
#pragma unroll
        for (int k2 = 0; k2 < 2; ++k2) {
            int row = rb0 + k2 * 16;
            size_t go = (size_t)(t * 256 + c0 + row) * 128 + segB * 8;
            *(uint4*)(smem + CV_BHI + row*272 + segB*16) = *(const uint4*)(g_wbf_hi + go);
            *(uint4*)(smem + CV_BLO + row*272 + segB*16) = *(const uint4*)(g_wbf_lo + go);
        }
        __syncthreads();

        const __nv_bfloat16* As_hi = (const __nv_bfloat16*)(smem + CV_AHI);
        const __nv_bfloat16* As_lo = (const __nv_bfloat16*)(smem + CV_ALO);
        const __nv_bfloat16* Bs_hi = (const __nv_bfloat16*)(smem + CV_BHI);
        const __nv_bfloat16* Bs_lo = (const __nv_bfloat16*)(smem + CV_BLO);

#pragma unroll
        for (int ks = 0; ks < 2; ++ks) {
            wmma::fragment<wmma::matrix_b, 16, 16, 16, __nv_bfloat16, wmma::row_major> bh[2], bl[2];
#pragma unroll
            for (int j = 0; j < 2; ++j) {
                wmma::load_matrix_sync(bh[j], Bs_hi + (ks*16)*136 + wn*32 + j*16, 136);
                wmma::load_matrix_sync(bl[j], Bs_lo + (ks*16)*136 + wn*32 + j*16, 136);
            }
#pragma unroll
            for (int i = 0; i < 4; ++i) {
                wmma::fragment<wmma::matrix_a, 16, 16, 16, __nv_bfloat16, wmma::row_major> ah, al;
                wmma::load_matrix_sync(ah, As_hi + (wm*64 + i*16)*40 + ks*16, 40);
                wmma::load_matrix_sync(al, As_lo + (wm*64 + i*16)*40 + ks*16, 40);
#pragma unroll
                for (int j = 0; j < 2; ++j) {
                    wmma::mma_sync(acc[i][j], ah, bh[j], acc[i][j]);
                    wmma::mma_sync(acc[i][j], ah, bl[j], acc[i][j]);
                    wmma::mma_sync(acc[i][j], al, bh[j], acc[i][j]);
                }
            }
        }
    }
    wmma_stage(smem, tid, acc);
    float* stage = (float*)smem;
    float* outp = g_queries + (size_t)l * HW * CC;
    for (int idx = tid; idx < 128*32; idx += 256) {
        int row = idx >> 5, sg = idx & 31;
        int grow = m0 + row;
        if (grow < HW) {
            float4 vv = *(float4*)(stage + row*132 + sg*4);
            float4 bb = *(const float4*)(conv_b + sg*4);
            vv.x += bb.x; vv.y += bb.y; vv.z += bb.z; vv.w += bb.w;
            *(float4*)(outp + (size_t)grow * CC + sg*4) = vv;
        }
    }
}

// ---------------- value projection via WMMA: [MQ x 128] @ W_val, scatter [l][h][p][dh] ----------------
__global__ __launch_bounds__(256) void value_wmma_kernel(const float* __restrict__ bv) {
    extern __shared__ char smem[];
    const int tid = threadIdx.x;
    const int m0 = blockIdx.x * 128;
    wmma::fragment<wmma::accumulator, 16, 16, 16, float> acc[4][2];
#pragma unroll
    for (int i = 0; i < 4; ++i)
#pragma unroll
        for (int j = 0; j < 2; ++j) wmma::fill_fragment(acc[i][j], 0.f);

    wmma_dense_loop(smem, tid, m0, MQ, g_src_hi, g_src_lo, CC,
                    g_wv_hi, g_wv_lo, CC, 0, 4, acc);
    wmma_stage(smem, tid, acc);
    float* stage = (float*)smem;
    for (int idx = tid; idx < 128*32; idx += 256) {
        int row = idx >> 5, sg = idx & 31;
        int grow = m0 + row;
        if (grow < MQ) {
            float4 vv = *(float4*)(stage + row*132 + sg*4);
            float4 bb = *(const float4*)(bv + sg*4);
            vv.x += bb.x; vv.y += bb.y; vv.z += bb.z; vv.w += bb.w;
            int l = grow / HW;
            int p = grow - l * HW;
            int col = sg * 4;
            int h = col >> 4, dd = col & 15;
            *(float4*)(g_value + ((size_t)(l*8 + h) * HW + p) * 16 + dd) = vv;
        }
    }
}

// ---------------- FFN1 via WMMA: relu(LN1out @ W1 + b1) -> bf16 hi/lo hidden ----------------
__global__ __launch_bounds__(256) void ffn1_wmma_kernel(const float* __restrict__ b1) {
    extern __shared__ char smem[];
    const int tid = threadIdx.x;
    const int m0 = blockIdx.x * 128;
    const int n0 = blockIdx.y * 128;
    wmma::fragment<wmma::accumulator, 16, 16, 16, float> acc[4][2];
#pragma unroll
    for (int i = 0; i < 4; ++i)
#pragma unroll
        for (int j = 0; j < 2; ++j) wmma::fill_fragment(acc[i][j], 0.f);

    wmma_dense_loop(smem, tid, m0, HW, g_srcbf_hi, g_srcbf_lo, CC,
                    g_w1_hi, g_w1_lo, DFF, n0, 4, acc);
    wmma_stage(smem, tid, acc);
    float* stage = (float*)smem;
    for (int idx = tid; idx < 128*32; idx += 256) {
        int row = idx >> 5, sg = idx & 31;
        int grow = m0 + row;
        if (grow < HW) {
            float4 vv = *(float4*)(stage + row*132 + sg*4);
            float4 bb = *(const float4*)(b1 + n0 + sg*4);
            float v0 = fmaxf(vv.x + bb.x, 0.f);
            float v1 = fmaxf(vv.y + bb.y, 0.f);
            float v2 = fmaxf(vv.z + bb.z, 0.f);
            float v3 = fmaxf(vv.w + bb.w, 0.f);
            __nv_bfloat16 h0 = __float2bfloat16(v0), h1 = __float2bfloat16(v1);
            __nv_bfloat16 h2 = __float2bfloat16(v2), h3 = __float2bfloat16(v3);
            __nv_bfloat16 l0 = __float2bfloat16(v0 - __bfloat162float(h0));
            __nv_bfloat16 l1 = __float2bfloat16(v1 - __bfloat162float(h1));
            __nv_bfloat16 l2 = __float2bfloat16(v2 - __bfloat162float(h2));
            __nv_bfloat16 l3 = __float2bfloat16(v3 - __bfloat162float(h3));
            size_t o = (size_t)grow * DFF + n0 + sg*4;
            __nv_bfloat162* ph = (__nv_bfloat162*)(g_hid_hi + o);
            __nv_bfloat162* pl = (__nv_bfloat162*)(g_hid_lo + o);
            ph[0] = __nv_bfloat162(h0, h1); ph[1] = __nv_bfloat162(h2, h3);
            pl[0] = __nv_bfloat162(l0, l1); pl[1] = __nv_bfloat162(l2, l3);
        }
    }
}

// ---------------- FFN2 + LN2 via WMMA: hidden @ W2 + b2 + residual -> LayerNorm -> out ----------------
__global__ __launch_bounds__(256) void ffn2_wmma_ln_kernel(const float* __restrict__ b2,
                                                           const float* __restrict__ gamma,
                                                           const float* __restrict__ beta,
                                                           float* __restrict__ out) {
    extern __shared__ char smem[];
    const int tid = threadIdx.x;
    const int m0 = blockIdx.x * 128;
    wmma::fragment<wmma::accumulator, 16, 16, 16, float> acc[4][2];
#pragma unroll
    for (int i = 0; i < 4; ++i)
#pragma unroll
        for (int j = 0; j < 2; ++j) wmma::fill_fragment(acc[i][j], 0.f);

    wmma_dense_loop(smem, tid, m0, HW, g_hid_hi, g_hid_lo, DFF,
                    g_w2_hi, g_w2_lo, CC, 0, 32, acc);
    wmma_stage(smem, tid, acc);
    float* stage = (float*)smem;

    // warp-per-row LN: each iteration, one warp's 32 lanes cover one row's 32 float4 segs
#pragma unroll
    for (int k = 0; k < 16; ++k) {
        int idx = tid + k * 256;
        int row = idx >> 5, sg = idx & 31;
        int grow = m0 + row;
        float4 vv = *(float4*)(stage + row*132 + sg*4);
        float4 bb = *(const float4*)(b2 + sg*4);
        float4 rr = make_float4(0.f,0.f,0.f,0.f);
        if (grow < HW) rr = *(const float4*)(g_src + (size_t)grow * CC + sg*4);
        vv.x += bb.x + rr.x; vv.y += bb.y + rr.y;
        vv.z += bb.z + rr.z; vv.w += bb.w + rr.w;
        float s  = vv.x + vv.y + vv.z + vv.w;
        float qq = vv.x*vv.x + vv.y*vv.y + vv.z*vv.z + vv.w*vv.w;
#pragma unroll
        for (int o = 16; o; o >>= 1) {
            s  += __shfl_xor_sync(0xFFFFFFFFu, s,  o);
            qq += __shfl_xor_sync(0xFFFFFFFFu, qq, o);
        }
        float m   = s * (1.0f / 128.0f);
        float var = qq * (1.0f / 128.0f) - m * m;
        float rst = rsqrtf(var + 1e-5f);
        if (grow < HW) {
            float4 gg = *(const float4*)(gamma + sg*4);
            float4 be = *(const float4*)(beta  + sg*4);
            float4 oo;
            oo.x = (vv.x - m) * rst * gg.x + be.x;
            oo.y = (vv.y - m) * rst * gg.y + be.y;
            oo.z = (vv.z - m) * rst * gg.z + be.z;
            oo.w = (vv.w - m) * rst * gg.w + be.w;
            *(float4*)(out + (size_t)grow * CC + sg*4) = oo;
        }
    }
}

// ---------------- offsets + attn logits: [MQ x 128] @ [128 x 96] (SIMT) ----------------
__global__ __launch_bounds__(256) void offattn_kernel(const float* __restrict__ W_off,
                                                      const float* __restrict__ b_off,
                                                      const float* __restrict__ W_attn,
                                                      const float* __restrict__ b_attn) {
    __shared__ __align__(16) float As[32][132];
    __shared__ __align__(16) float Bs[32][96];
    const int m0 = blockIdx.x * 128;
    const int tid = threadIdx.x;
    const int tx = tid & 15, ty = tid >> 4;
    float acc[8][6];
#pragma unroll
    for (int i = 0; i < 8; ++i)
#pragma unroll
        for (int j = 0; j < 6; ++j) acc[i][j] = 0.f;

    float4 pa[4];
#pragma unroll
    for (int it = 0; it < 4; ++it) {
        int li = tid + it * 256;
        int gm = m0 + (li >> 3);
        pa[it] = make_float4(0.f,0.f,0.f,0.f);
        if (gm < MQ) pa[it] = *(const float4*)(g_queries + (size_t)gm * CC + ((li & 7) << 2));
    }

    for (int cc = 0; cc < 4; ++cc) {
        const int k0 = cc * 32;
        __syncthreads();
#pragma unroll
        for (int it = 0; it < 4; ++it) {
            int li = tid + it * 256;
            int r  = li >> 3;
            int kv = (li & 7) << 2;
            As[kv+0][r] = pa[it].x; As[kv+1][r] = pa[it].y;
            As[kv+2][r] = pa[it].z; As[kv+3][r] = pa[it].w;
        }
#pragma unroll
        for (int it = 0; it < 3; ++it) {
            int li = tid + it * 256;
            int kk = li / 24;
            int nv = (li % 24) << 2;
            float4 v;
            if (nv < 64) v = *(const float4*)(W_off  + (size_t)(k0 + kk) * 64 + nv);
            else         v = *(const float4*)(W_attn + (size_t)(k0 + kk) * 32 + (nv - 64));
            *(float4*)&Bs[kk][nv] = v;
        }
        __syncthreads();
        if (cc < 3) {
            const int kn = k0 + 32;
#pragma unroll
            for (int it = 0; it < 4; ++it) {
                int li = tid + it * 256;
                int gm = m0 + (li >> 3);
                pa[it] = make_float4(0.f,0.f,0.f,0.f);
                if (gm < MQ) pa[it] = *(const float4*)(g_queries + (size_t)gm * CC + kn + ((li & 7) << 2));
            }
        }
#pragma unroll
        for (int k = 0; k < 32; ++k) {
            float a[8];
            *(float4*)&a[0] = *(const float4*)&As[k][ty*8];
            *(float4*)&a[4] = *(const float4*)&As[k][ty*8+4];
            float b[6];
#pragma unroll
            for (int j = 0; j < 6; ++j) b[j] = Bs[k][tx*6 + j];
#pragma unroll
            for (int i = 0; i < 8; ++i)
#pragma unroll
                for (int j = 0; j < 6; ++j)
                    acc[i][j] = fmaf(a[i], b[j], acc[i][j]);
        }
    }
#pragma unroll
    for (int i = 0; i < 8; ++i) {
        int row = m0 + ty*8 + i;
        if (row < MQ) {
#pragma unroll
            for (int j = 0; j < 6; ++j) {
                int col = tx*6 + j;
                float bias = (col < 64) ? b_off[col] : b_attn[col - 64];
                g_offattn[(size_t)row * 96 + col] = acc[i][j] + bias;
            }
        }
    }
}

// ---------------- deformable sampling + softmax + weighted sum (2 queries/block) ----------------
__global__ __launch_bounds__(256) void sample_kernel(const float* __restrict__ refpts) {
    __shared__ float oa[2][3][96];
    __shared__ float rp[2][6];
    const int q0 = blockIdx.x * 2;
    const int tid = threadIdx.x;
    const int sq = tid >> 7;
    const int t  = tid & 127;
    const int q  = q0 + sq;

    for (int i = tid; i < 2*288; i += 256) {
        int qq = i / 288;
        int rem = i - qq * 288;
        int l = rem / 96, j = rem - l * 96;
        oa[qq][l][j] = g_offattn[((size_t)l * HW + q0 + qq) * 96 + j];
    }
    if (tid < 12) rp[tid / 6][tid % 6] = refpts[(size_t)q0 * 6 + tid];
    __syncthreads();

    const int h = t >> 4, d = t & 15;
    float mx = -1e30f;
#pragma unroll
    for (int l = 0; l < 3; ++l)
#pragma unroll
        for (int p = 0; p < 4; ++p) mx = fmaxf(mx, oa[sq][l][64 + h*4 + p]);
    float den = 0.f;
#pragma unroll
    for (int l = 0; l < 3; ++l)
#pragma unroll
        for (int p = 0; p < 4; ++p) den += expf(oa[sq][l][64 + h*4 + p] - mx);
    const float inv = 1.0f / den;

    float acc = 0.f;
#pragma unroll
    for (int l = 0; l < 3; ++l) {
        const float rx = rp[sq][l*2 + 0], ry = rp[sq][l*2 + 1];
        const float* vb = g_value + (size_t)(l*8 + h) * HW * 16 + d;

        float w00[4], w01[4], w10[4], w11[4], aw[4];
        int o00[4], o01[4], o10[4], o11[4];
#pragma unroll
        for (int p = 0; p < 4; ++p) {
            float ox = oa[sq][l][h*8 + p*2 + 0];
            float oy = oa[sq][l][h*8 + p*2 + 1];
            aw[p] = expf(oa[sq][l][64 + h*4 + p] - mx) * inv;
            float px = (rx + ox * (1.0f/180.0f)) * 180.0f - 0.5f;
            float py = (ry + oy * (1.0f/180.0f)) * 180.0f - 0.5f;
            float xf = floorf(px), yf = floorf(py);
            int x0 = (int)xf, y0 = (int)yf;
            float fx = px - xf, fy = py - yf;
            float vx0 = (x0   >= 0 && x0   < WIW) ? 1.f : 0.f;
            float vx1 = (x0+1 >= 0 && x0+1 < WIW) ? 1.f : 0.f;
            float vy0 = (y0   >= 0 && y0   < HH)  ? 1.f : 0.f;
            float vy1 = (y0+1 >= 0 && y0+1 < HH)  ? 1.f : 0.f;
            int cx0 = min(max(x0,     0), WIW-1);
            int cx1 = min(max(x0 + 1, 0), WIW-1);
            int cy0 = min(max(y0,     0), HH-1);
            int cy1 = min(max(y0 + 1, 0), HH-1);
            w00[p] = (1.f-fx)*(1.f-fy) * vx0 * vy0;
            w01[p] = fx      *(1.f-fy) * vx1 * vy0;
            w10[p] = (1.f-fx)*fy       * vx0 * vy1;
            w11[p] = fx      *fy       * vx1 * vy1;
            o00[p] = (cy0 * WIW + cx0) * 16;
            o01[p] = (cy0 * WIW + cx1) * 16;
            o10[p] = (cy1 * WIW + cx0) * 16;
            o11[p] = (cy1 * WIW + cx1) * 16;
        }

        float g00[4], g01[4], g10[4], g11[4];
#pragma unroll
        for (int p = 0; p < 4; ++p) {
            g00[p] = vb[o00[p]];
            g01[p] = vb[o01[p]];
            g10[p] = vb[o10[p]];
            g11[p] = vb[o11[p]];
        }
#pragma unroll
        for (int p = 0; p < 4; ++p) {
            float s = w00[p]*g00[p] + w01[p]*g01[p] + w10[p]*g10[p] + w11[p]*g11[p];
            acc = fmaf(aw[p], s, acc);
        }
    }
    g_attnout[(size_t)q * CC + t] = acc;
}

// ---------------- out-proj GEMM + bias + residual + LayerNorm (SIMT, K=128) ----------------
// Also writes bf16 hi/lo split of the LN output for the WMMA FFN1 to consume.
__global__ __launch_bounds__(256) void gemm_ln_kernel(const float* __restrict__ A,
                                                      const float* __restrict__ Bw,
                                                      const float* __restrict__ bias,
                                                      const float* __restrict__ res,
                                                      const float* __restrict__ gamma,
                                                      const float* __restrict__ beta,
                                                      float* __restrict__ out) {
    __shared__ __align__(16) float As[32][132];
    __shared__ __align__(16) float Bs[32][132];
    const int m0 = blockIdx.x * 128;
    const int tid = threadIdx.x;
    const int tx = tid & 15, ty = tid >> 4;
    float acc[8][8];
#pragma unroll
    for (int i = 0; i < 8; ++i)
#pragma unroll
        for (int j = 0; j < 8; ++j) acc[i][j] = 0.f;

    float4 pa[4];
#pragma unroll
    for (int it = 0; it < 4; ++it) {
        int li = tid + it * 256;
        int gm = m0 + (li >> 3);
        pa[it] = make_float4(0.f,0.f,0.f,0.f);
        if (gm < HW) pa[it] = *(const float4*)(A + (size_t)gm * CC + ((li & 7) << 2));
    }

    for (int cc = 0; cc < 4; ++cc) {
        const int k0 = cc * 32;
        __syncthreads();
#pragma unroll
        for (int it = 0; it < 4; ++it) {
            int li = tid + it * 256;
            int r  = li >> 3;
            int kv = (li & 7) << 2;
            As[kv+0][r] = pa[it].x; As[kv+1][r] = pa[it].y;
            As[kv+2][r] = pa[it].z; As[kv+3][r] = pa[it].w;
        }
#pragma unroll
        for (int it = 0; it < 4; ++it) {
            int li = tid + it * 256;
            int kk = li >> 5;
            int nv = (li & 31) << 2;
            *(float4*)&Bs[kk][nv] = *(const float4*)(Bw + (size_t)(k0 + kk) * CC + nv);
        }
        __syncthreads();
        if (cc < 3) {
            const int kn = k0 + 32;
#pragma unroll
            for (int it = 0; it < 4; ++it) {
                int li = tid + it * 256;
                int gm = m0 + (li >> 3);
                pa[it] = make_float4(0.f,0.f,0.f,0.f);
                if (gm < HW) pa[it] = *(const float4*)(A + (size_t)gm * CC + kn + ((li & 7) << 2));
            }
        }
#pragma unroll
        for (int k = 0; k < 32; ++k) {
            float a[8], b[8];
            *(float4*)&a[0] = *(const float4*)&As[k][ty*8];
            *(float4*)&a[4] = *(const float4*)&As[k][ty*8+4];
            *(float4*)&b[0] = *(const float4*)&Bs[k][tx*8];
            *(float4*)&b[4] = *(const float4*)&Bs[k][tx*8+4];
#pragma unroll
            for (int i = 0; i < 8; ++i)
#pragma unroll
                for (int j = 0; j < 8; ++j)
                    acc[i][j] = fmaf(a[i], b[j], acc[i][j]);
        }
    }
    __syncthreads();
    float* rs     = &As[0][0];
    float* rq     = rs + 2048;
    float* mean_s = &Bs[0][0];
    float* rstd_s = mean_s + 128;

#pragma unroll
    for (int i = 0; i < 8; ++i) {
        int row = m0 + ty*8 + i;
        float s = 0.f, qq = 0.f;
#pragma unroll
        for (int j = 0; j < 8; ++j) {
            int col = tx*8 + j;
            float v = acc[i][j] + bias[col] + ((row < HW) ? res[(size_t)row * CC + col] : 0.f);
            acc[i][j] = v;
            s += v; qq += v * v;
        }
        rs[(ty*8 + i) * 16 + tx] = s;
        rq[(ty*8 + i) * 16 + tx] = qq;
    }
    __syncthreads();
    if (tid < 128) {
        float s = 0.f, qq = 0.f;
#pragma unroll
        for (int u = 0; u < 16; ++u) { s += rs[tid*16 + u]; qq += rq[tid*16 + u]; }
        float m = s * (1.0f / 128.0f);
        float v = qq * (1.0f / 128.0f) - m * m;
        mean_s[tid] = m;
        rstd_s[tid] = rsqrtf(v + 1e-5f);
    }
    __syncthreads();
#pragma unroll
    for (int i = 0; i < 8; ++i) {
        int row = m0 + ty*8 + i;
        if (row < HW) {
            float m = mean_s[ty*8 + i], rst = rstd_s[ty*8 + i];
#pragma unroll
            for (int j = 0; j < 8; ++j) {
                int col = tx*8 + j;
                float val = (acc[i][j] - m) * rst * gamma[col] + beta[col];
                size_t o = (size_t)row * CC + col;
                out[o] = val;
                __nv_bfloat16 hi = __float2bfloat16(val);
                g_srcbf_hi[o] = hi;
                g_srcbf_lo[o] = __float2bfloat16(val - __bfloat162float(hi));
            }
        }
    }
}

// ---------------- launch ----------------
extern "C" void kernel_launch(void* const* d_in, const int* in_sizes, int n_in,
                              void* d_out, int out_size) {
    const float* src_all  = (const float*)d_in[0];
    const float* refpts   = (const float*)d_in[1];
    const float* conv_w   = (const float*)d_in[3];
    const float* conv_b   = (const float*)d_in[4];
    const float* W_val    = (const float*)d_in[5];
    const float* b_val    = (const float*)d_in[6];
    const float* W_off    = (const float*)d_in[7];
    const float* b_off    = (const float*)d_in[8];
    const float* W_attn   = (const float*)d_in[9];
    const float* b_attn   = (const float*)d_in[10];
    const float* W_out    = (const float*)d_in[11];
    const float* b_out    = (const float*)d_in[12];
    const float* ln1_g    = (const float*)d_in[13];
    const float* ln1_b    = (const float*)d_in[14];
    const float* W1       = (const float*)d_in[15];
    const float* b1       = (const float*)d_in[16];
    const float* W2       = (const float*)d_in[17];
    const float* b2       = (const float*)d_in[18];
    const float* ln2_g    = (const float*)d_in[19];
    const float* ln2_b    = (const float*)d_in[20];
    float* outp = (float*)d_out;

    float *p_attnout, *p_src;
    cudaGetSymbolAddress((void**)&p_attnout, g_attnout);
    cudaGetSymbolAddress((void**)&p_src, g_src);
    __nv_bfloat16 *p_wv_hi, *p_wv_lo, *p_w1_hi, *p_w1_lo, *p_w2_hi, *p_w2_lo;
    cudaGetSymbolAddress((void**)&p_wv_hi, g_wv_hi);
    cudaGetSymbolAddress((void**)&p_wv_lo, g_wv_lo);
    cudaGetSymbolAddress((void**)&p_w1_hi, g_w1_hi);
    cudaGetSymbolAddress((void**)&p_w1_lo, g_w1_lo);
    cudaGetSymbolAddress((void**)&p_w2_hi, g_w2_hi);
    cudaGetSymbolAddress((void**)&p_w2_lo, g_w2_lo);

    cudaFuncSetAttribute(conv_wmma_kernel, cudaFuncAttributeMaxDynamicSharedMemorySize, CV_SMEM);
    cudaFuncSetAttribute(value_wmma_kernel, cudaFuncAttributeMaxDynamicSharedMemorySize, CV_SMEM);
    cudaFuncSetAttribute(ffn1_wmma_kernel, cudaFuncAttributeMaxDynamicSharedMemorySize, CV_SMEM);
    cudaFuncSetAttribute(ffn2_wmma_ln_kernel, cudaFuncAttributeMaxDynamicSharedMemorySize, CV_SMEM);

    const int MT  = (HW + 127) / 128;      // 254
    const int MQT = (MQ + 127) / 128;      // 760
    const size_t NSRC = (size_t)LVL*HW*CC; // 12.44M

    split_src_kernel<<<(unsigned)((NSRC + 255) / 256), 256>>>(src_all);
    wsplit_kernel<<<(9*256*128 + 255)/256, 256>>>(conv_w);
    wsplit_mat_kernel<<<(128*128 + 255)/256, 256>>>(W_val, p_wv_hi, p_wv_lo, 128*128);
    wsplit_mat_kernel<<<(128*1024 + 255)/256, 256>>>(W1, p_w1_hi, p_w1_lo, 128*1024);
    wsplit_mat_kernel<<<(1024*128 + 255)/256, 256>>>(W2, p_w2_hi, p_w2_lo, 1024*128);
    conv_wmma_kernel<<<dim3(MT, LVL), 256, CV_SMEM>>>(conv_b);
    value_wmma_kernel<<<MQT, 256, CV_SMEM>>>(b_val);
    offattn_kernel<<<MQT, 256>>>(W_off, b_off, W_attn, b_attn);
    sample_kernel<<<HW/2, 256>>>(refpts);
    gemm_ln_kernel<<<MT, 256>>>(p_attnout, W_out, b_out, src_all, ln1_g, ln1_b, p_src);
    ffn1_wmma_kernel<<<dim3(MT, DFF/128), 256, CV_SMEM>>>(b1);
    ffn2_wmma_ln_kernel<<<MT, 256, CV_SMEM>>>(b2, ln2_g, ln2_b, outp);
}